// round 14
// baseline (speedup 1.0000x reference)
#include <cuda_runtime.h>
#include <math.h>
#include <stdint.h>

#define BATCH 2
#define SEQ 2048
#define DIM 1024
#define NHEAD 16
#define HDIM 64
#define MROWS (BATCH*SEQ)     // 4096
#define NBUCKET 64
#define KSPLIT 4

// ---------------- scratch (device globals: no allocation allowed) ----------------
__device__ float g_Q[MROWS*DIM];
__device__ float g_K[MROWS*DIM];
__device__ float g_V[MROWS*DIM];
__device__ float g_AO[MROWS*DIM];    // written tf32-rounded by attention
__device__ float g_Xr[3*MROWS*DIM];  // tf32-rounded query/key/value
__device__ float g_Wt[4*DIM*DIM];    // transposed + tf32-rounded Wq/Wk/Wv/Wo ([n][k])
__device__ float g_Tq[DIM*NBUCKET];
__device__ float g_Tk[DIM*NBUCKET];
__device__ float g_blsh[2*NBUCKET];
__device__ float g_Pp[2*KSPLIT*MROWS*NBUCKET];   // K-split partials
__device__ int   g_Qh[MROWS];
__device__ int   g_Kh[MROWS];
__device__ int   g_Qidx[MROWS];
__device__ int   g_Kidx[MROWS];
__device__ int   g_Koff[BATCH*(NBUCKET+1)];
__device__ int   g_Qoff[BATCH*(NBUCKET+1)];
__device__ float g_meanV[BATCH*DIM];
__device__ float g_mpart[16*DIM];

__device__ __forceinline__ float* scratch_ptr(int sel) {
    switch (sel) {
        case 0: return g_Q;
        case 1: return g_K;
        case 2: return g_V;
        case 3: return g_AO;
        case 4: return g_Xr;
        case 5: return g_Xr + (size_t)MROWS*DIM;
        case 6: return g_Xr + (size_t)2*MROWS*DIM;
    }
    return nullptr;
}

__device__ __forceinline__ float tf32r(float x) {
    uint32_t u = __float_as_uint(x);
    asm("cvt.rna.tf32.f32 %0, %0;" : "+r"(u));
    return __uint_as_float(u);
}

// ---------------- tf32 pre-round of query/key/value -> g_Xr ----------------
__global__ __launch_bounds__(256)
void roundX_kernel(const float* __restrict__ q, const float* __restrict__ k,
                   const float* __restrict__ v) {
    const int z = blockIdx.y;
    const float* src = (z == 0) ? q : (z == 1) ? k : v;
    float* dst = g_Xr + (size_t)z * MROWS * DIM;
    const int i = (blockIdx.x * 256 + threadIdx.x) * 4;
    const float4 a = *(const float4*)&src[i];
    float4 o;
    o.x = tf32r(a.x); o.y = tf32r(a.y); o.z = tf32r(a.z); o.w = tf32r(a.w);
    *(float4*)&dst[i] = o;
}

// ---------------- weight transpose + tf32 round: g_Wt[z][n][k] ----------------
__global__ __launch_bounds__(256)
void transposeW_kernel(const float* __restrict__ Wq, const float* __restrict__ Wk,
                       const float* __restrict__ Wv, const float* __restrict__ Wo) {
    const float* W;
    switch (blockIdx.z) {
        case 0: W = Wq; break;
        case 1: W = Wk; break;
        case 2: W = Wv; break;
        default: W = Wo; break;
    }
    float* Wt = g_Wt + (size_t)blockIdx.z * DIM * DIM;

    __shared__ float t[32][33];
    const int tx = threadIdx.x;
    const int ty = threadIdx.y;
    const int k0 = blockIdx.y * 32;
    const int n0 = blockIdx.x * 32;

    #pragma unroll
    for (int i = 0; i < 4; i++)
        t[ty + i * 8][tx] = W[(size_t)(k0 + ty + i * 8) * DIM + n0 + tx];
    __syncthreads();
    #pragma unroll
    for (int i = 0; i < 4; i++)
        Wt[(size_t)(n0 + ty + i * 8) * DIM + k0 + tx] = tf32r(t[tx][ty + i * 8]);
}

// =====================================================================
// tf32 tensor-core GEMM (round-12 proven): C = A @ W + bias.
// Operands PRE-ROUNDED tf32; W transposed ([n][k]); B via ldmatrix.x2.
// BM=BN=128, BK=32, 256 thr (8 warps 2x4), double-buffered cp.async.
// =====================================================================
#define TBM 128
#define TBN 128
#define TBK 32
#define AS_LD 36
#define BS_LD 36
#define AS_STRIDE (TBM*AS_LD)        // 4608
#define BS_STRIDE (TBN*BS_LD)        // 4608
#define TF32_SMEM_BYTES (2*(AS_STRIDE+BS_STRIDE)*4)   // 73728

struct GemmArgs {
    const float* bias[3];
    float* Cext[3];
    int asel[3];
    int bwsel[3];   // index into g_Wt (0..3)
    int csel[3];
};

__global__ __launch_bounds__(256, 2)
void gemm_tf32_kernel(GemmArgs args, int M, int N, int K) {
    const int z = blockIdx.z;
    const float* A = scratch_ptr(args.asel[z]);
    const float* Bt = g_Wt + (size_t)args.bwsel[z] * DIM * DIM;   // [N][K]
    const float* bias = args.bias[z];
    float* C = (args.csel[z] >= 0) ? scratch_ptr(args.csel[z]) : args.Cext[z];

    extern __shared__ float dynsmem[];
    float* As = dynsmem;
    float* Bs = dynsmem + 2 * AS_STRIDE;

    const int tid  = threadIdx.x;
    const int lane = tid & 31;
    const int warp = tid >> 5;
    const int wm = warp >> 2;
    const int wn = warp & 3;
    const int bm = blockIdx.y * TBM;
    const int bn = blockIdx.x * TBN;

    const int lrow = lane & 7;
    const int lsel = lane >> 3;
    const int arow_base = wm * 64 + ((lsel & 1) << 3) + lrow;
    const int acol_base = (lsel >> 1) << 2;
    const int bksel = ((lane >> 3) & 1) << 2;

    float acc[4][4][4];
    #pragma unroll
    for (int i = 0; i < 4; i++)
        #pragma unroll
        for (int j = 0; j < 4; j++)
            #pragma unroll
            for (int r = 0; r < 4; r++) acc[i][j][r] = 0.f;

    auto load_stage = [&](int buf, int k0) {
        float* AsB = As + buf * AS_STRIDE;
        float* BsB = Bs + buf * BS_STRIDE;
        #pragma unroll
        for (int i = 0; i < 4; i++) {
            int idx = tid + 256 * i;
            int r = idx >> 3, c4 = (idx & 7) << 2;
            const float* src = A + (size_t)(bm + r) * K + k0 + c4;
            uint32_t dst = (uint32_t)__cvta_generic_to_shared(&AsB[r * AS_LD + c4]);
            asm volatile("cp.async.ca.shared.global [%0], [%1], 16;\n" :: "r"(dst), "l"(src));
        }
        #pragma unroll
        for (int i = 0; i < 4; i++) {
            int idx = tid + 256 * i;
            int r = idx >> 3, c4 = (idx & 7) << 2;
            const float* src = Bt + (size_t)(bn + r) * K + k0 + c4;
            uint32_t dst = (uint32_t)__cvta_generic_to_shared(&BsB[r * BS_LD + c4]);
            asm volatile("cp.async.ca.shared.global [%0], [%1], 16;\n" :: "r"(dst), "l"(src));
        }
    };

    auto compute_stage = [&](int buf) {
        const float* AsB = As + buf * AS_STRIDE;
        const float* BsB = Bs + buf * BS_STRIDE;
        #pragma unroll
        for (int ks = 0; ks < 4; ks++) {
            const int k8 = ks * 8;
            uint32_t afr[4][4];
            #pragma unroll
            for (int mt = 0; mt < 4; mt++) {
                const float* p = &AsB[(arow_base + mt * 16) * AS_LD + k8 + acol_base];
                uint32_t sa = (uint32_t)__cvta_generic_to_shared(p);
                asm volatile("ldmatrix.sync.aligned.m8n8.x4.shared.b16 {%0,%1,%2,%3}, [%4];\n"
                    : "=r"(afr[mt][0]), "=r"(afr[mt][1]), "=r"(afr[mt][2]), "=r"(afr[mt][3])
                    : "r"(sa));
            }
            #pragma unroll
            for (int nt = 0; nt < 4; nt++) {
                const float* bp = &BsB[(wn * 32 + nt * 8 + lrow) * BS_LD + k8 + bksel];
                uint32_t sb = (uint32_t)__cvta_generic_to_shared(bp);
                uint32_t b0, b1;
                asm volatile("ldmatrix.sync.aligned.m8n8.x2.shared.b16 {%0,%1}, [%2];\n"
                    : "=r"(b0), "=r"(b1) : "r"(sb));
                #pragma unroll
                for (int mt = 0; mt < 4; mt++) {
                    asm volatile(
                        "mma.sync.aligned.m16n8k8.row.col.f32.tf32.tf32.f32 "
                        "{%0,%1,%2,%3}, {%4,%5,%6,%7}, {%8,%9}, {%0,%1,%2,%3};\n"
                        : "+f"(acc[mt][nt][0]), "+f"(acc[mt][nt][1]),
                          "+f"(acc[mt][nt][2]), "+f"(acc[mt][nt][3])
                        : "r"(afr[mt][0]), "r"(afr[mt][1]), "r"(afr[mt][2]), "r"(afr[mt][3]),
                          "r"(b0), "r"(b1));
                }
            }
        }
    };

    const int KT = K >> 5;
    load_stage(0, 0);
    asm volatile("cp.async.commit_group;\n");
    for (int kt = 0; kt < KT; kt++) {
        if (kt + 1 < KT) load_stage((kt + 1) & 1, (kt + 1) << 5);
        asm volatile("cp.async.commit_group;\n");
        asm volatile("cp.async.wait_group 1;\n");
        __syncthreads();
        compute_stage(kt & 1);
        __syncthreads();
    }

    #pragma unroll
    for (int nt = 0; nt < 4; nt++) {
        const int col = bn + wn * 32 + nt * 8 + ((lane & 3) << 1);
        float bb0 = 0.f, bb1 = 0.f;
        if (bias) { bb0 = bias[col]; bb1 = bias[col + 1]; }
        #pragma unroll
        for (int mt = 0; mt < 4; mt++) {
            const int row = bm + wm * 64 + mt * 16 + (lane >> 2);
            float2 v0 = make_float2(acc[mt][nt][0] + bb0, acc[mt][nt][1] + bb1);
            float2 v1 = make_float2(acc[mt][nt][2] + bb0, acc[mt][nt][3] + bb1);
            *(float2*)&C[(size_t)row * N + col] = v0;
            *(float2*)&C[(size_t)(row + 8) * N + col] = v1;
        }
    }
}

// =====================================================================
// fp32 N=64 GEMM partials, K-split. __launch_bounds__(256,4) caps regs
// at 64 -> 4 blocks/SM (was 128 regs / 25% occ, latency-bound).
// =====================================================================
__global__ __launch_bounds__(256, 4)
void nk64_part_kernel(const float* __restrict__ Xq, const float* __restrict__ Xk,
                      const float* __restrict__ lshp, int mode) {
    const int z = blockIdx.z;
    const int ksp = blockIdx.y;
    const float* X = z ? Xk : Xq;
    const float* Bm = (mode == 0) ? lshp : (z ? g_Tk : g_Tq);

    __shared__ float Xs[64][33];
    __shared__ float Bs2[32][68];

    const int tid = threadIdx.x;
    const int ty = tid >> 4;
    const int tx = tid & 15;
    const int bm = blockIdx.x * 64;
    const int kbeg = ksp * (DIM / KSPLIT);
    const int kend = kbeg + (DIM / KSPLIT);

    float acc[4][4];
    #pragma unroll
    for (int i = 0; i < 4; i++)
        #pragma unroll
        for (int j = 0; j < 4; j++) acc[i][j] = 0.f;

    for (int k0 = kbeg; k0 < kend; k0 += 32) {
        #pragma unroll
        for (int i = 0; i < 8; i++) {
            int idx = tid + 256 * i;
            int r = idx >> 5, c = idx & 31;
            Xs[r][c] = X[(size_t)(bm + r) * DIM + k0 + c];
        }
        #pragma unroll
        for (int i = 0; i < 8; i++) {
            int idx = tid + 256 * i;
            int r = idx >> 6, c = idx & 63;
            Bs2[r][c] = Bm[(size_t)(k0 + r) * NBUCKET + c];
        }
        __syncthreads();
        #pragma unroll
        for (int kk = 0; kk < 32; kk++) {
            float a0 = Xs[ty * 4 + 0][kk];
            float a1 = Xs[ty * 4 + 1][kk];
            float a2 = Xs[ty * 4 + 2][kk];
            float a3 = Xs[ty * 4 + 3][kk];
            float4 b = *(const float4*)&Bs2[kk][tx * 4];
            acc[0][0] = fmaf(a0, b.x, acc[0][0]); acc[0][1] = fmaf(a0, b.y, acc[0][1]);
            acc[0][2] = fmaf(a0, b.z, acc[0][2]); acc[0][3] = fmaf(a0, b.w, acc[0][3]);
            acc[1][0] = fmaf(a1, b.x, acc[1][0]); acc[1][1] = fmaf(a1, b.y, acc[1][1]);
            acc[1][2] = fmaf(a1, b.z, acc[1][2]); acc[1][3] = fmaf(a1, b.w, acc[1][3]);
            acc[2][0] = fmaf(a2, b.x, acc[2][0]); acc[2][1] = fmaf(a2, b.y, acc[2][1]);
            acc[2][2] = fmaf(a2, b.z, acc[2][2]); acc[2][3] = fmaf(a2, b.w, acc[2][3]);
            acc[3][0] = fmaf(a3, b.x, acc[3][0]); acc[3][1] = fmaf(a3, b.y, acc[3][1]);
            acc[3][2] = fmaf(a3, b.z, acc[3][2]); acc[3][3] = fmaf(a3, b.w, acc[3][3]);
        }
        __syncthreads();
    }

    float* out = g_Pp + ((size_t)(z * KSPLIT + ksp) * MROWS) * NBUCKET;
    #pragma unroll
    for (int i = 0; i < 4; i++) {
        float4 v = make_float4(acc[i][0], acc[i][1], acc[i][2], acc[i][3]);
        *(float4*)&out[(size_t)(bm + ty * 4 + i) * NBUCKET + tx * 4] = v;
    }
}

__global__ void reduceT_kernel() {
    const int z = blockIdx.y;
    int i = blockIdx.x * 512 + threadIdx.x;
    float s = 0.f;
    #pragma unroll
    for (int p = 0; p < KSPLIT; p++)
        s += g_Pp[((size_t)(z * KSPLIT + p) * MROWS) * NBUCKET + i];
    (z ? g_Tk : g_Tq)[i] = s;
}

__global__ __launch_bounds__(256)
void reduceP_argmax_kernel() {
    const int z = blockIdx.y;
    const int lane = threadIdx.x & 31;
    const int warp = threadIdx.x >> 5;
    const int row = blockIdx.x * 8 + warp;
    const float* bv = g_blsh + z * NBUCKET;

    float va = bv[lane], vb = bv[lane + 32];
    #pragma unroll
    for (int p = 0; p < KSPLIT; p++) {
        const float* pp = g_Pp + (((size_t)(z * KSPLIT + p) * MROWS) + row) * NBUCKET;
        va += pp[lane];
        vb += pp[lane + 32];
    }
    int ia = lane;
    if (vb > va) { va = vb; ia = lane + 32; }
    #pragma unroll
    for (int o = 16; o > 0; o >>= 1) {
        float vo = __shfl_xor_sync(0xffffffffu, va, o);
        int io = __shfl_xor_sync(0xffffffffu, ia, o);
        if (vo > va || (vo == va && io < ia)) { va = vo; ia = io; }
    }
    if (lane == 0) (z ? g_Kh : g_Qh)[row] = ia;
}

// bvec: one block per (j, z); 128-thread reduction over 1024 elements.
__global__ __launch_bounds__(128)
void bvec_kernel(const float* __restrict__ bq, const float* __restrict__ bk,
                 const float* __restrict__ lsh) {
    const int j = blockIdx.x;
    const int z = blockIdx.y;
    const int tid = threadIdx.x;
    const float* bb = z ? bk : bq;
    float s = 0.f;
    #pragma unroll
    for (int o = tid; o < DIM; o += 128)
        s = fmaf(bb[o], lsh[o * NBUCKET + j], s);
    __shared__ float red[128];
    red[tid] = s;
    __syncthreads();
    if (tid < 64) { red[tid] += red[tid + 64]; }
    __syncthreads();
    if (tid < 32) {
        float v = red[tid] + red[tid + 32];
        #pragma unroll
        for (int o = 16; o > 0; o >>= 1) v += __shfl_xor_sync(0xffffffffu, v, o);
        if (tid == 0) g_blsh[z * NBUCKET + j] = v;
    }
}

// ---------------- parallel stable counting sort ----------------
__global__ __launch_bounds__(1024)
void sort_kernel() {
    const int b = blockIdx.x;
    const int which = blockIdx.y;
    const int* h = (which ? g_Kh : g_Qh) + b * SEQ;
    int* sidx    = (which ? g_Kidx : g_Qidx) + b * SEQ;
    int* goff    = (which ? g_Koff : g_Qoff) + b * (NBUCKET + 1);

    __shared__ int hist[NBUCKET];
    __shared__ int off[NBUCKET];
    __shared__ int wc[32][NBUCKET];
    __shared__ int wcp[32][NBUCKET];

    const int tid = threadIdx.x;
    const int lane = tid & 31;
    const int warp = tid >> 5;

    if (tid < NBUCKET) hist[tid] = 0;
    __syncthreads();
    const int e0 = h[tid];
    const int e1 = h[tid + 1024];
    atomicAdd(&hist[e0], 1);
    atomicAdd(&hist[e1], 1);
    __syncthreads();
    if (tid == 0) {
        int run = 0;
        for (int i = 0; i < NBUCKET; i++) { int c = hist[i]; hist[i] = run; run += c; }
    }
    __syncthreads();
    if (tid < NBUCKET) goff[tid] = hist[tid];
    if (tid == 0)      goff[NBUCKET] = SEQ;
    if (tid < NBUCKET) off[tid] = hist[tid];
    __syncthreads();

    #pragma unroll
    for (int c = 0; c < 2; c++) {
        for (int i = tid; i < 32 * NBUCKET; i += 1024) (&wc[0][0])[i] = 0;
        __syncthreads();
        const int e = (c == 0) ? e0 : e1;
        unsigned mask = __match_any_sync(0xffffffffu, e);
        int rank = __popc(mask & ((1u << lane) - 1));
        if ((int)(__ffs(mask) - 1) == lane) wc[warp][e] = __popc(mask);
        __syncthreads();
        if (tid < NBUCKET) {
            int run = off[tid];
            #pragma unroll 8
            for (int w = 0; w < 32; w++) {
                int t = wc[w][tid];
                wcp[w][tid] = run;
                run += t;
            }
            off[tid] = run;
        }
        __syncthreads();
        int pos = wcp[warp][e] + rank;
        sidx[pos] = c * 1024 + tid;
        __syncthreads();
    }
}

// ---------------- mean of projected V (two-stage) ----------------
__global__ void meanv1_kernel() {
    const int b = blockIdx.x;
    const int p = blockIdx.y;
    const int d = threadIdx.x;
    const float* v = g_V + (size_t)b * SEQ * DIM + (size_t)p * 256 * DIM + d;
    float s = 0.f;
    for (int t = 0; t < 256; t++) s += v[(size_t)t * DIM];
    g_mpart[(b * 8 + p) * DIM + d] = s;
}
__global__ void meanv2_kernel() {
    const int b = blockIdx.x;
    const int d = threadIdx.x;
    float s = 0.f;
    #pragma unroll
    for (int p = 0; p < 8; p++) s += g_mpart[(b * 8 + p) * DIM + d];
    g_meanV[b * DIM + d] = s * (1.0f / (float)SEQ);
}

// ---------------- bucket-block attention; AO stores tf32-rounded ----------------
#define CK 64
__global__ __launch_bounds__(256)
void attn_bucket_kernel() {
    const int t = blockIdx.x;
    const int h = blockIdx.y;
    const int b = blockIdx.z;
    const int tid = threadIdx.x;
    const int lane = tid & 31;
    const int w = tid >> 5;

    const int qs = g_Qoff[b * (NBUCKET + 1) + t];
    const int qe = g_Qoff[b * (NBUCKET + 1) + t + 1];
    if (qs == qe) return;
    const int ks = g_Koff[b * (NBUCKET + 1) + t];
    const int ke = g_Koff[b * (NBUCKET + 1) + t + 1];

    float* AOb = g_AO + (size_t)(b * SEQ) * DIM + h * HDIM;

    if (ks == ke) {
        const float mv0 = tf32r(g_meanV[b * DIM + h * HDIM + lane]);
        const float mv1 = tf32r(g_meanV[b * DIM + h * HDIM + lane + 32]);
        for (int q = qs + w; q < qe; q += 8) {
            AOb[(size_t)q * DIM + lane]      = mv0;
            AOb[(size_t)q * DIM + lane + 32] = mv1;
        }
        return;
    }

    __shared__ float Ks[CK][68];
    __shared__ float Vs[CK][68];

    const int* kidx = g_Kidx + b * SEQ;
    const int* qidx = g_Qidx + b * SEQ;
    const float* Qb = g_Q + (size_t)(b * SEQ) * DIM + h * HDIM;
    const float* Kb = g_K + (size_t)(b * SEQ) * DIM + h * HDIM;
    const float* Vb = g_V + (size_t)(b * SEQ) * DIM + h * HDIM;
    const int nk = ke - ks;

    for (int qt = qs; qt < qe; qt += 8) {
        const int myq = qt + w;
        const bool active = (myq < qe);
        float qr0 = 0.f, qr1 = 0.f;
        if (active) {
            const float* qp = Qb + (size_t)qidx[myq] * DIM;
            qr0 = qp[lane];
            qr1 = qp[lane + 32];
        }
        float m = -3.402823466e38f, l = 0.f, a0 = 0.f, a1 = 0.f;

        for (int c0 = 0; c0 < nk; c0 += CK) {
            const int cn = min(CK, nk - c0);
            __syncthreads();
            for (int i = tid; i < cn * 16; i += 256) {
                const int r = i >> 4, c4 = (i & 15) << 2;
                const int gr = kidx[ks + c0 + r];
                *(float4*)&Ks[r][c4] = *(const float4*)&Kb[(size_t)gr * DIM + c4];
                *(float4*)&Vs[r][c4] = *(const float4*)&Vb[(size_t)gr * DIM + c4];
            }
            __syncthreads();
            if (!active) continue;

            int r = 0;
            for (; r + 4 <= cn; r += 4) {
                float s0 = qr0 * Ks[r + 0][lane] + qr1 * Ks[r + 0][lane + 32];
                float s1 = qr0 * Ks[r + 1][lane] + qr1 * Ks[r + 1][lane + 32];
                float s2 = qr0 * Ks[r + 2][lane] + qr1 * Ks[r + 2][lane + 32];
                float s3 = qr0 * Ks[r + 3][lane] + qr1 * Ks[r + 3][lane + 32];
                #pragma unroll
                for (int o = 16; o > 0; o >>= 1) {
                    s0 += __shfl_xor_sync(0xffffffffu, s0, o);
                    s1 += __shfl_xor_sync(0xffffffffu, s1, o);
                    s2 += __shfl_xor_sync(0xffffffffu, s2, o);
                    s3 += __shfl_xor_sync(0xffffffffu, s3, o);
                }
                s0 *= 0.125f; s1 *= 0.125f; s2 *= 0.125f; s3 *= 0.125f;
                const float mn = fmaxf(m, fmaxf(fmaxf(s0, s1), fmaxf(s2, s3)));
                const float cold = expf(m - mn);
                const float p0 = expf(s0 - mn);
                const float p1 = expf(s1 - mn);
                const float p2 = expf(s2 - mn);
                const float p3 = expf(s3 - mn);
                l = l * cold + (p0 + p1 + p2 + p3);
                a0 = a0 * cold + p0 * Vs[r + 0][lane] + p1 * Vs[r + 1][lane]
                               + p2 * Vs[r + 2][lane] + p3 * Vs[r + 3][lane];
                a1 = a1 * cold + p0 * Vs[r + 0][lane + 32] + p1 * Vs[r + 1][lane + 32]
                               + p2 * Vs[r + 2][lane + 32] + p3 * Vs[r + 3][lane + 32];
                m = mn;
            }
            for (; r < cn; r++) {
                float s = qr0 * Ks[r][lane] + qr1 * Ks[r][lane + 32];
                #pragma unroll
                for (int o = 16; o > 0; o >>= 1) s += __shfl_xor_sync(0xffffffffu, s, o);
                s *= 0.125f;
                const float mn = fmaxf(m, s);
                const float cold = expf(m - mn);
                const float p = expf(s - mn);
                l = l * cold + p;
                a0 = a0 * cold + p * Vs[r][lane];
                a1 = a1 * cold + p * Vs[r][lane + 32];
                m = mn;
            }
        }

        if (active) {
            const float inv = 1.f / l;
            AOb[(size_t)myq * DIM + lane]      = tf32r(a0 * inv);
            AOb[(size_t)myq * DIM + lane + 32] = tf32r(a1 * inv);
        }
    }
}

// ---------------- launch ----------------
extern "C" void kernel_launch(void* const* d_in, const int* in_sizes, int n_in,
                              void* d_out, int out_size) {
    const float* query = (const float*)d_in[0];
    const float* key   = (const float*)d_in[1];
    const float* value = (const float*)d_in[2];
    const float* Wq = (const float*)d_in[3];
    const float* bq = (const float*)d_in[4];
    const float* Wk = (const float*)d_in[5];
    const float* bk = (const float*)d_in[6];
    const float* Wv = (const float*)d_in[7];
    const float* bv = (const float*)d_in[8];
    const float* Wo = (const float*)d_in[9];
    const float* bo = (const float*)d_in[10];
    const float* lsh = (const float*)d_in[11];
    float* out = (float*)d_out;

    cudaFuncSetAttribute(gemm_tf32_kernel,
                         cudaFuncAttributeMaxDynamicSharedMemorySize, TF32_SMEM_BYTES);

    const dim3 blk(256);

    // nk64 mode-1 placed at launch #4 this round to verify the regcap delta.
    roundX_kernel<<<dim3(MROWS * DIM / 1024, 3), blk>>>(query, key, value);    // 1
    transposeW_kernel<<<dim3(32, 32, 4), dim3(32, 8)>>>(Wq, Wk, Wv, Wo);       // 2
    nk64_part_kernel<<<dim3(DIM / 64, KSPLIT, 2), blk>>>(Wq, Wk, lsh, 0);      // 3
    reduceT_kernel<<<dim3(DIM * NBUCKET / 512, 2), 512>>>();                   // (3b)

    // 4 (approx): nk64 mode-1 — PROFILED LAUNCH target
    nk64_part_kernel<<<dim3(MROWS / 64, KSPLIT, 2), blk>>>(query, key, lsh, 1);

    // tf32 input projections, batched z=3
    {
        GemmArgs ga;
        ga.bias[0] = bq; ga.bias[1] = bk; ga.bias[2] = bv;
        ga.Cext[0] = ga.Cext[1] = ga.Cext[2] = nullptr;
        ga.asel[0] = 4; ga.asel[1] = 5; ga.asel[2] = 6;
        ga.bwsel[0] = 0; ga.bwsel[1] = 1; ga.bwsel[2] = 2;
        ga.csel[0] = 0; ga.csel[1] = 1; ga.csel[2] = 2;
        gemm_tf32_kernel<<<dim3(DIM / TBN, MROWS / TBM, 3), blk, TF32_SMEM_BYTES>>>(ga, MROWS, DIM, DIM);
    }

    bvec_kernel<<<dim3(NBUCKET, 2), 128>>>(bq, bk, lsh);
    reduceP_argmax_kernel<<<dim3(MROWS / 8, 2), blk>>>();
    sort_kernel<<<dim3(BATCH, 2), 1024>>>();

    meanv1_kernel<<<dim3(BATCH, 8), DIM>>>();
    meanv2_kernel<<<BATCH, DIM>>>();

    attn_bucket_kernel<<<dim3(NBUCKET, NHEAD, BATCH), blk>>>();

    // tf32 output projection (AO already tf32-rounded by attention)
    {
        GemmArgs ga;
        ga.bias[0] = bo; ga.bias[1] = nullptr; ga.bias[2] = nullptr;
        ga.Cext[0] = out; ga.Cext[1] = nullptr; ga.Cext[2] = nullptr;
        ga.asel[0] = 3; ga.asel[1] = 3; ga.asel[2] = 3;
        ga.bwsel[0] = 3; ga.bwsel[1] = 3; ga.bwsel[2] = 3;
        ga.csel[0] = -1; ga.csel[1] = -1; ga.csel[2] = -1;
        gemm_tf32_kernel<<<dim3(DIM / TBN, MROWS / TBM, 1), blk, TF32_SMEM_BYTES>>>(ga, MROWS, DIM, DIM);
    }
}

// round 15
// speedup vs baseline: 1.0311x; 1.0311x over previous
#include <cuda_runtime.h>
#include <math.h>
#include <stdint.h>

#define BATCH 2
#define SEQ 2048
#define DIM 1024
#define NHEAD 16
#define HDIM 64
#define MROWS (BATCH*SEQ)     // 4096
#define NBUCKET 64
#define KSPLIT 4

// ---------------- scratch (device globals: no allocation allowed) ----------------
__device__ float g_Q[MROWS*DIM];
__device__ float g_K[MROWS*DIM];
__device__ float g_V[MROWS*DIM];
__device__ float g_AO[MROWS*DIM];    // written tf32-rounded by attention
__device__ float g_Xr[3*MROWS*DIM];  // tf32-rounded query/key/value
__device__ float g_Wt[4*DIM*DIM];    // transposed + tf32-rounded Wq/Wk/Wv/Wo ([n][k])
__device__ float g_Tq[DIM*NBUCKET];
__device__ float g_Tk[DIM*NBUCKET];
__device__ float g_blsh[2*NBUCKET];
__device__ float g_Pp[2*KSPLIT*MROWS*NBUCKET];   // K-split partials
__device__ int   g_Qh[MROWS];
__device__ int   g_Kh[MROWS];
__device__ int   g_Qidx[MROWS];
__device__ int   g_Kidx[MROWS];
__device__ int   g_Koff[BATCH*(NBUCKET+1)];
__device__ int   g_Qoff[BATCH*(NBUCKET+1)];
__device__ float g_meanV[BATCH*DIM];
__device__ float g_mpart[16*DIM];

__device__ __forceinline__ float* scratch_ptr(int sel) {
    switch (sel) {
        case 0: return g_Q;
        case 1: return g_K;
        case 2: return g_V;
        case 3: return g_AO;
        case 4: return g_Xr;
        case 5: return g_Xr + (size_t)MROWS*DIM;
        case 6: return g_Xr + (size_t)2*MROWS*DIM;
    }
    return nullptr;
}

__device__ __forceinline__ float tf32r(float x) {
    uint32_t u = __float_as_uint(x);
    asm("cvt.rna.tf32.f32 %0, %0;" : "+r"(u));
    return __uint_as_float(u);
}

// ---------------- tf32 pre-round of query/key/value -> g_Xr ----------------
__global__ __launch_bounds__(256)
void roundX_kernel(const float* __restrict__ q, const float* __restrict__ k,
                   const float* __restrict__ v) {
    const int z = blockIdx.y;
    const float* src = (z == 0) ? q : (z == 1) ? k : v;
    float* dst = g_Xr + (size_t)z * MROWS * DIM;
    const int i = (blockIdx.x * 256 + threadIdx.x) * 4;
    const float4 a = *(const float4*)&src[i];
    float4 o;
    o.x = tf32r(a.x); o.y = tf32r(a.y); o.z = tf32r(a.z); o.w = tf32r(a.w);
    *(float4*)&dst[i] = o;
}

// ---------------- weight transpose + tf32 round: g_Wt[z][n][k] ----------------
__global__ __launch_bounds__(256)
void transposeW_kernel(const float* __restrict__ Wq, const float* __restrict__ Wk,
                       const float* __restrict__ Wv, const float* __restrict__ Wo) {
    const float* W;
    switch (blockIdx.z) {
        case 0: W = Wq; break;
        case 1: W = Wk; break;
        case 2: W = Wv; break;
        default: W = Wo; break;
    }
    float* Wt = g_Wt + (size_t)blockIdx.z * DIM * DIM;

    __shared__ float t[32][33];
    const int tx = threadIdx.x;
    const int ty = threadIdx.y;
    const int k0 = blockIdx.y * 32;
    const int n0 = blockIdx.x * 32;

    #pragma unroll
    for (int i = 0; i < 4; i++)
        t[ty + i * 8][tx] = W[(size_t)(k0 + ty + i * 8) * DIM + n0 + tx];
    __syncthreads();
    #pragma unroll
    for (int i = 0; i < 4; i++)
        Wt[(size_t)(n0 + ty + i * 8) * DIM + k0 + tx] = tf32r(t[tx][ty + i * 8]);
}

// =====================================================================
// tf32 tensor-core GEMM (round-12 proven): C = A @ W + bias.
// Operands PRE-ROUNDED tf32; W transposed ([n][k]); B via ldmatrix.x2.
// BM=BN=128, BK=32, 256 thr (8 warps 2x4), double-buffered cp.async.
// =====================================================================
#define TBM 128
#define TBN 128
#define TBK 32
#define AS_LD 36
#define BS_LD 36
#define AS_STRIDE (TBM*AS_LD)        // 4608
#define BS_STRIDE (TBN*BS_LD)        // 4608
#define TF32_SMEM_BYTES (2*(AS_STRIDE+BS_STRIDE)*4)   // 73728

struct GemmArgs {
    const float* bias[3];
    float* Cext[3];
    int asel[3];
    int bwsel[3];   // index into g_Wt (0..3)
    int csel[3];
};

__global__ __launch_bounds__(256, 2)
void gemm_tf32_kernel(GemmArgs args, int M, int N, int K) {
    const int z = blockIdx.z;
    const float* A = scratch_ptr(args.asel[z]);
    const float* Bt = g_Wt + (size_t)args.bwsel[z] * DIM * DIM;   // [N][K]
    const float* bias = args.bias[z];
    float* C = (args.csel[z] >= 0) ? scratch_ptr(args.csel[z]) : args.Cext[z];

    extern __shared__ float dynsmem[];
    float* As = dynsmem;
    float* Bs = dynsmem + 2 * AS_STRIDE;

    const int tid  = threadIdx.x;
    const int lane = tid & 31;
    const int warp = tid >> 5;
    const int wm = warp >> 2;
    const int wn = warp & 3;
    const int bm = blockIdx.y * TBM;
    const int bn = blockIdx.x * TBN;

    const int lrow = lane & 7;
    const int lsel = lane >> 3;
    const int arow_base = wm * 64 + ((lsel & 1) << 3) + lrow;
    const int acol_base = (lsel >> 1) << 2;
    const int bksel = ((lane >> 3) & 1) << 2;

    float acc[4][4][4];
    #pragma unroll
    for (int i = 0; i < 4; i++)
        #pragma unroll
        for (int j = 0; j < 4; j++)
            #pragma unroll
            for (int r = 0; r < 4; r++) acc[i][j][r] = 0.f;

    auto load_stage = [&](int buf, int k0) {
        float* AsB = As + buf * AS_STRIDE;
        float* BsB = Bs + buf * BS_STRIDE;
        #pragma unroll
        for (int i = 0; i < 4; i++) {
            int idx = tid + 256 * i;
            int r = idx >> 3, c4 = (idx & 7) << 2;
            const float* src = A + (size_t)(bm + r) * K + k0 + c4;
            uint32_t dst = (uint32_t)__cvta_generic_to_shared(&AsB[r * AS_LD + c4]);
            asm volatile("cp.async.ca.shared.global [%0], [%1], 16;\n" :: "r"(dst), "l"(src));
        }
        #pragma unroll
        for (int i = 0; i < 4; i++) {
            int idx = tid + 256 * i;
            int r = idx >> 3, c4 = (idx & 7) << 2;
            const float* src = Bt + (size_t)(bn + r) * K + k0 + c4;
            uint32_t dst = (uint32_t)__cvta_generic_to_shared(&BsB[r * BS_LD + c4]);
            asm volatile("cp.async.ca.shared.global [%0], [%1], 16;\n" :: "r"(dst), "l"(src));
        }
    };

    auto compute_stage = [&](int buf) {
        const float* AsB = As + buf * AS_STRIDE;
        const float* BsB = Bs + buf * BS_STRIDE;
        #pragma unroll
        for (int ks = 0; ks < 4; ks++) {
            const int k8 = ks * 8;
            uint32_t afr[4][4];
            #pragma unroll
            for (int mt = 0; mt < 4; mt++) {
                const float* p = &AsB[(arow_base + mt * 16) * AS_LD + k8 + acol_base];
                uint32_t sa = (uint32_t)__cvta_generic_to_shared(p);
                asm volatile("ldmatrix.sync.aligned.m8n8.x4.shared.b16 {%0,%1,%2,%3}, [%4];\n"
                    : "=r"(afr[mt][0]), "=r"(afr[mt][1]), "=r"(afr[mt][2]), "=r"(afr[mt][3])
                    : "r"(sa));
            }
            #pragma unroll
            for (int nt = 0; nt < 4; nt++) {
                const float* bp = &BsB[(wn * 32 + nt * 8 + lrow) * BS_LD + k8 + bksel];
                uint32_t sb = (uint32_t)__cvta_generic_to_shared(bp);
                uint32_t b0, b1;
                asm volatile("ldmatrix.sync.aligned.m8n8.x2.shared.b16 {%0,%1}, [%2];\n"
                    : "=r"(b0), "=r"(b1) : "r"(sb));
                #pragma unroll
                for (int mt = 0; mt < 4; mt++) {
                    asm volatile(
                        "mma.sync.aligned.m16n8k8.row.col.f32.tf32.tf32.f32 "
                        "{%0,%1,%2,%3}, {%4,%5,%6,%7}, {%8,%9}, {%0,%1,%2,%3};\n"
                        : "+f"(acc[mt][nt][0]), "+f"(acc[mt][nt][1]),
                          "+f"(acc[mt][nt][2]), "+f"(acc[mt][nt][3])
                        : "r"(afr[mt][0]), "r"(afr[mt][1]), "r"(afr[mt][2]), "r"(afr[mt][3]),
                          "r"(b0), "r"(b1));
                }
            }
        }
    };

    const int KT = K >> 5;
    load_stage(0, 0);
    asm volatile("cp.async.commit_group;\n");
    for (int kt = 0; kt < KT; kt++) {
        if (kt + 1 < KT) load_stage((kt + 1) & 1, (kt + 1) << 5);
        asm volatile("cp.async.commit_group;\n");
        asm volatile("cp.async.wait_group 1;\n");
        __syncthreads();
        compute_stage(kt & 1);
        __syncthreads();
    }

    #pragma unroll
    for (int nt = 0; nt < 4; nt++) {
        const int col = bn + wn * 32 + nt * 8 + ((lane & 3) << 1);
        float bb0 = 0.f, bb1 = 0.f;
        if (bias) { bb0 = bias[col]; bb1 = bias[col + 1]; }
        #pragma unroll
        for (int mt = 0; mt < 4; mt++) {
            const int row = bm + wm * 64 + mt * 16 + (lane >> 2);
            float2 v0 = make_float2(acc[mt][nt][0] + bb0, acc[mt][nt][1] + bb1);
            float2 v1 = make_float2(acc[mt][nt][2] + bb0, acc[mt][nt][3] + bb1);
            *(float2*)&C[(size_t)row * N + col] = v0;
            *(float2*)&C[(size_t)(row + 8) * N + col] = v1;
        }
    }
}

// =====================================================================
// fp32 N=64 GEMM partials, K-split (round-12 exact version)
// =====================================================================
__global__ __launch_bounds__(256)
void nk64_part_kernel(const float* __restrict__ Xq, const float* __restrict__ Xk,
                      const float* __restrict__ lshp, int mode) {
    const int z = blockIdx.z;
    const int ksp = blockIdx.y;
    const float* X = z ? Xk : Xq;
    const float* Bm = (mode == 0) ? lshp : (z ? g_Tk : g_Tq);

    __shared__ float Xs[64][33];
    __shared__ float Bs2[32][68];

    const int tid = threadIdx.x;
    const int ty = tid >> 4;
    const int tx = tid & 15;
    const int bm = blockIdx.x * 64;
    const int kbeg = ksp * (DIM / KSPLIT);
    const int kend = kbeg + (DIM / KSPLIT);

    float acc[4][4];
    #pragma unroll
    for (int i = 0; i < 4; i++)
        #pragma unroll
        for (int j = 0; j < 4; j++) acc[i][j] = 0.f;

    for (int k0 = kbeg; k0 < kend; k0 += 32) {
        #pragma unroll
        for (int i = 0; i < 8; i++) {
            int idx = tid + 256 * i;
            int r = idx >> 5, c = idx & 31;
            Xs[r][c] = X[(size_t)(bm + r) * DIM + k0 + c];
        }
        #pragma unroll
        for (int i = 0; i < 8; i++) {
            int idx = tid + 256 * i;
            int r = idx >> 6, c = idx & 63;
            Bs2[r][c] = Bm[(size_t)(k0 + r) * NBUCKET + c];
        }
        __syncthreads();
        #pragma unroll
        for (int kk = 0; kk < 32; kk++) {
            float a0 = Xs[ty * 4 + 0][kk];
            float a1 = Xs[ty * 4 + 1][kk];
            float a2 = Xs[ty * 4 + 2][kk];
            float a3 = Xs[ty * 4 + 3][kk];
            float4 b = *(const float4*)&Bs2[kk][tx * 4];
            acc[0][0] = fmaf(a0, b.x, acc[0][0]); acc[0][1] = fmaf(a0, b.y, acc[0][1]);
            acc[0][2] = fmaf(a0, b.z, acc[0][2]); acc[0][3] = fmaf(a0, b.w, acc[0][3]);
            acc[1][0] = fmaf(a1, b.x, acc[1][0]); acc[1][1] = fmaf(a1, b.y, acc[1][1]);
            acc[1][2] = fmaf(a1, b.z, acc[1][2]); acc[1][3] = fmaf(a1, b.w, acc[1][3]);
            acc[2][0] = fmaf(a2, b.x, acc[2][0]); acc[2][1] = fmaf(a2, b.y, acc[2][1]);
            acc[2][2] = fmaf(a2, b.z, acc[2][2]); acc[2][3] = fmaf(a2, b.w, acc[2][3]);
            acc[3][0] = fmaf(a3, b.x, acc[3][0]); acc[3][1] = fmaf(a3, b.y, acc[3][1]);
            acc[3][2] = fmaf(a3, b.z, acc[3][2]); acc[3][3] = fmaf(a3, b.w, acc[3][3]);
        }
        __syncthreads();
    }

    float* out = g_Pp + ((size_t)(z * KSPLIT + ksp) * MROWS) * NBUCKET;
    #pragma unroll
    for (int i = 0; i < 4; i++) {
        float4 v = make_float4(acc[i][0], acc[i][1], acc[i][2], acc[i][3]);
        *(float4*)&out[(size_t)(bm + ty * 4 + i) * NBUCKET + tx * 4] = v;
    }
}

__global__ void reduceT_kernel() {
    const int z = blockIdx.y;
    int i = blockIdx.x * 512 + threadIdx.x;
    float s = 0.f;
    #pragma unroll
    for (int p = 0; p < KSPLIT; p++)
        s += g_Pp[((size_t)(z * KSPLIT + p) * MROWS) * NBUCKET + i];
    (z ? g_Tk : g_Tq)[i] = s;
}

__global__ __launch_bounds__(256)
void reduceP_argmax_kernel() {
    const int z = blockIdx.y;
    const int lane = threadIdx.x & 31;
    const int warp = threadIdx.x >> 5;
    const int row = blockIdx.x * 8 + warp;
    const float* bv = g_blsh + z * NBUCKET;

    float va = bv[lane], vb = bv[lane + 32];
    #pragma unroll
    for (int p = 0; p < KSPLIT; p++) {
        const float* pp = g_Pp + (((size_t)(z * KSPLIT + p) * MROWS) + row) * NBUCKET;
        va += pp[lane];
        vb += pp[lane + 32];
    }
    int ia = lane;
    if (vb > va) { va = vb; ia = lane + 32; }
    #pragma unroll
    for (int o = 16; o > 0; o >>= 1) {
        float vo = __shfl_xor_sync(0xffffffffu, va, o);
        int io = __shfl_xor_sync(0xffffffffu, ia, o);
        if (vo > va || (vo == va && io < ia)) { va = vo; ia = io; }
    }
    if (lane == 0) (z ? g_Kh : g_Qh)[row] = ia;
}

// bvec: one block per (j, z); 128-thread reduction over 1024 elements.
__global__ __launch_bounds__(128)
void bvec_kernel(const float* __restrict__ bq, const float* __restrict__ bk,
                 const float* __restrict__ lsh) {
    const int j = blockIdx.x;
    const int z = blockIdx.y;
    const int tid = threadIdx.x;
    const float* bb = z ? bk : bq;
    float s = 0.f;
    #pragma unroll
    for (int o = tid; o < DIM; o += 128)
        s = fmaf(bb[o], lsh[o * NBUCKET + j], s);
    __shared__ float red[128];
    red[tid] = s;
    __syncthreads();
    if (tid < 64) { red[tid] += red[tid + 64]; }
    __syncthreads();
    if (tid < 32) {
        float v = red[tid] + red[tid + 32];
        #pragma unroll
        for (int o = 16; o > 0; o >>= 1) v += __shfl_xor_sync(0xffffffffu, v, o);
        if (tid == 0) g_blsh[z * NBUCKET + j] = v;
    }
}

// ---------------- parallel stable counting sort ----------------
__global__ __launch_bounds__(1024)
void sort_kernel() {
    const int b = blockIdx.x;
    const int which = blockIdx.y;
    const int* h = (which ? g_Kh : g_Qh) + b * SEQ;
    int* sidx    = (which ? g_Kidx : g_Qidx) + b * SEQ;
    int* goff    = (which ? g_Koff : g_Qoff) + b * (NBUCKET + 1);

    __shared__ int hist[NBUCKET];
    __shared__ int off[NBUCKET];
    __shared__ int wc[32][NBUCKET];
    __shared__ int wcp[32][NBUCKET];

    const int tid = threadIdx.x;
    const int lane = tid & 31;
    const int warp = tid >> 5;

    if (tid < NBUCKET) hist[tid] = 0;
    __syncthreads();
    const int e0 = h[tid];
    const int e1 = h[tid + 1024];
    atomicAdd(&hist[e0], 1);
    atomicAdd(&hist[e1], 1);
    __syncthreads();
    if (tid == 0) {
        int run = 0;
        for (int i = 0; i < NBUCKET; i++) { int c = hist[i]; hist[i] = run; run += c; }
    }
    __syncthreads();
    if (tid < NBUCKET) goff[tid] = hist[tid];
    if (tid == 0)      goff[NBUCKET] = SEQ;
    if (tid < NBUCKET) off[tid] = hist[tid];
    __syncthreads();

    #pragma unroll
    for (int c = 0; c < 2; c++) {
        for (int i = tid; i < 32 * NBUCKET; i += 1024) (&wc[0][0])[i] = 0;
        __syncthreads();
        const int e = (c == 0) ? e0 : e1;
        unsigned mask = __match_any_sync(0xffffffffu, e);
        int rank = __popc(mask & ((1u << lane) - 1));
        if ((int)(__ffs(mask) - 1) == lane) wc[warp][e] = __popc(mask);
        __syncthreads();
        if (tid < NBUCKET) {
            int run = off[tid];
            #pragma unroll 8
            for (int w = 0; w < 32; w++) {
                int t = wc[w][tid];
                wcp[w][tid] = run;
                run += t;
            }
            off[tid] = run;
        }
        __syncthreads();
        int pos = wcp[warp][e] + rank;
        sidx[pos] = c * 1024 + tid;
        __syncthreads();
    }
}

// ---------------- mean of projected V (two-stage) ----------------
__global__ void meanv1_kernel() {
    const int b = blockIdx.x;
    const int p = blockIdx.y;
    const int d = threadIdx.x;
    const float* v = g_V + (size_t)b * SEQ * DIM + (size_t)p * 256 * DIM + d;
    float s = 0.f;
    for (int t = 0; t < 256; t++) s += v[(size_t)t * DIM];
    g_mpart[(b * 8 + p) * DIM + d] = s;
}
__global__ void meanv2_kernel() {
    const int b = blockIdx.x;
    const int d = threadIdx.x;
    float s = 0.f;
    #pragma unroll
    for (int p = 0; p < 8; p++) s += g_mpart[(b * 8 + p) * DIM + d];
    g_meanV[b * DIM + d] = s * (1.0f / (float)SEQ);
}

// ---------------- bucket-block attention; AO stores tf32-rounded ----------------
// Small buckets (nk <= CK): stage K/V ONCE, loop query tiles with no
// restaging and no barriers. Large buckets: chunked path (unchanged).
#define CK 64
__global__ __launch_bounds__(256)
void attn_bucket_kernel() {
    const int t = blockIdx.x;
    const int h = blockIdx.y;
    const int b = blockIdx.z;
    const int tid = threadIdx.x;
    const int lane = tid & 31;
    const int w = tid >> 5;

    const int qs = g_Qoff[b * (NBUCKET + 1) + t];
    const int qe = g_Qoff[b * (NBUCKET + 1) + t + 1];
    if (qs == qe) return;
    const int ks = g_Koff[b * (NBUCKET + 1) + t];
    const int ke = g_Koff[b * (NBUCKET + 1) + t + 1];

    float* AOb = g_AO + (size_t)(b * SEQ) * DIM + h * HDIM;

    if (ks == ke) {
        const float mv0 = tf32r(g_meanV[b * DIM + h * HDIM + lane]);
        const float mv1 = tf32r(g_meanV[b * DIM + h * HDIM + lane + 32]);
        for (int q = qs + w; q < qe; q += 8) {
            AOb[(size_t)q * DIM + lane]      = mv0;
            AOb[(size_t)q * DIM + lane + 32] = mv1;
        }
        return;
    }

    __shared__ float Ks[CK][68];
    __shared__ float Vs[CK][68];

    const int* kidx = g_Kidx + b * SEQ;
    const int* qidx = g_Qidx + b * SEQ;
    const float* Qb = g_Q + (size_t)(b * SEQ) * DIM + h * HDIM;
    const float* Kb = g_K + (size_t)(b * SEQ) * DIM + h * HDIM;
    const float* Vb = g_V + (size_t)(b * SEQ) * DIM + h * HDIM;
    const int nk = ke - ks;

    if (nk <= CK) {
        // ---- single-chunk fast path: stage once ----
        for (int i = tid; i < nk * 16; i += 256) {
            const int r = i >> 4, c4 = (i & 15) << 2;
            const int gr = kidx[ks + r];
            *(float4*)&Ks[r][c4] = *(const float4*)&Kb[(size_t)gr * DIM + c4];
            *(float4*)&Vs[r][c4] = *(const float4*)&Vb[(size_t)gr * DIM + c4];
        }
        __syncthreads();

        for (int myq = qs + w; myq < qe; myq += 8) {
            const float* qp = Qb + (size_t)qidx[myq] * DIM;
            const float qr0 = qp[lane];
            const float qr1 = qp[lane + 32];

            float m = -3.402823466e38f, l = 0.f, a0 = 0.f, a1 = 0.f;
            int r = 0;
            for (; r + 4 <= nk; r += 4) {
                float s0 = qr0 * Ks[r + 0][lane] + qr1 * Ks[r + 0][lane + 32];
                float s1 = qr0 * Ks[r + 1][lane] + qr1 * Ks[r + 1][lane + 32];
                float s2 = qr0 * Ks[r + 2][lane] + qr1 * Ks[r + 2][lane + 32];
                float s3 = qr0 * Ks[r + 3][lane] + qr1 * Ks[r + 3][lane + 32];
                #pragma unroll
                for (int o = 16; o > 0; o >>= 1) {
                    s0 += __shfl_xor_sync(0xffffffffu, s0, o);
                    s1 += __shfl_xor_sync(0xffffffffu, s1, o);
                    s2 += __shfl_xor_sync(0xffffffffu, s2, o);
                    s3 += __shfl_xor_sync(0xffffffffu, s3, o);
                }
                s0 *= 0.125f; s1 *= 0.125f; s2 *= 0.125f; s3 *= 0.125f;
                const float mn = fmaxf(m, fmaxf(fmaxf(s0, s1), fmaxf(s2, s3)));
                const float cold = expf(m - mn);
                const float p0 = expf(s0 - mn);
                const float p1 = expf(s1 - mn);
                const float p2 = expf(s2 - mn);
                const float p3 = expf(s3 - mn);
                l = l * cold + (p0 + p1 + p2 + p3);
                a0 = a0 * cold + p0 * Vs[r + 0][lane] + p1 * Vs[r + 1][lane]
                               + p2 * Vs[r + 2][lane] + p3 * Vs[r + 3][lane];
                a1 = a1 * cold + p0 * Vs[r + 0][lane + 32] + p1 * Vs[r + 1][lane + 32]
                               + p2 * Vs[r + 2][lane + 32] + p3 * Vs[r + 3][lane + 32];
                m = mn;
            }
            for (; r < nk; r++) {
                float s = qr0 * Ks[r][lane] + qr1 * Ks[r][lane + 32];
                #pragma unroll
                for (int o = 16; o > 0; o >>= 1) s += __shfl_xor_sync(0xffffffffu, s, o);
                s *= 0.125f;
                const float mn = fmaxf(m, s);
                const float cold = expf(m - mn);
                const float p = expf(s - mn);
                l = l * cold + p;
                a0 = a0 * cold + p * Vs[r][lane];
                a1 = a1 * cold + p * Vs[r][lane + 32];
                m = mn;
            }
            const float inv = 1.f / l;
            AOb[(size_t)myq * DIM + lane]      = tf32r(a0 * inv);
            AOb[(size_t)myq * DIM + lane + 32] = tf32r(a1 * inv);
        }
        return;
    }

    // ---- large-bucket chunked path (unchanged) ----
    for (int qt = qs; qt < qe; qt += 8) {
        const int myq = qt + w;
        const bool active = (myq < qe);
        float qr0 = 0.f, qr1 = 0.f;
        if (active) {
            const float* qp = Qb + (size_t)qidx[myq] * DIM;
            qr0 = qp[lane];
            qr1 = qp[lane + 32];
        }
        float m = -3.402823466e38f, l = 0.f, a0 = 0.f, a1 = 0.f;

        for (int c0 = 0; c0 < nk; c0 += CK) {
            const int cn = min(CK, nk - c0);
            __syncthreads();
            for (int i = tid; i < cn * 16; i += 256) {
                const int r = i >> 4, c4 = (i & 15) << 2;
                const int gr = kidx[ks + c0 + r];
                *(float4*)&Ks[r][c4] = *(const float4*)&Kb[(size_t)gr * DIM + c4];
                *(float4*)&Vs[r][c4] = *(const float4*)&Vb[(size_t)gr * DIM + c4];
            }
            __syncthreads();
            if (!active) continue;

            int r = 0;
            for (; r + 4 <= cn; r += 4) {
                float s0 = qr0 * Ks[r + 0][lane] + qr1 * Ks[r + 0][lane + 32];
                float s1 = qr0 * Ks[r + 1][lane] + qr1 * Ks[r + 1][lane + 32];
                float s2 = qr0 * Ks[r + 2][lane] + qr1 * Ks[r + 2][lane + 32];
                float s3 = qr0 * Ks[r + 3][lane] + qr1 * Ks[r + 3][lane + 32];
                #pragma unroll
                for (int o = 16; o > 0; o >>= 1) {
                    s0 += __shfl_xor_sync(0xffffffffu, s0, o);
                    s1 += __shfl_xor_sync(0xffffffffu, s1, o);
                    s2 += __shfl_xor_sync(0xffffffffu, s2, o);
                    s3 += __shfl_xor_sync(0xffffffffu, s3, o);
                }
                s0 *= 0.125f; s1 *= 0.125f; s2 *= 0.125f; s3 *= 0.125f;
                const float mn = fmaxf(m, fmaxf(fmaxf(s0, s1), fmaxf(s2, s3)));
                const float cold = expf(m - mn);
                const float p0 = expf(s0 - mn);
                const float p1 = expf(s1 - mn);
                const float p2 = expf(s2 - mn);
                const float p3 = expf(s3 - mn);
                l = l * cold + (p0 + p1 + p2 + p3);
                a0 = a0 * cold + p0 * Vs[r + 0][lane] + p1 * Vs[r + 1][lane]
                               + p2 * Vs[r + 2][lane] + p3 * Vs[r + 3][lane];
                a1 = a1 * cold + p0 * Vs[r + 0][lane + 32] + p1 * Vs[r + 1][lane + 32]
                               + p2 * Vs[r + 2][lane + 32] + p3 * Vs[r + 3][lane + 32];
                m = mn;
            }
            for (; r < cn; r++) {
                float s = qr0 * Ks[r][lane] + qr1 * Ks[r][lane + 32];
                #pragma unroll
                for (int o = 16; o > 0; o >>= 1) s += __shfl_xor_sync(0xffffffffu, s, o);
                s *= 0.125f;
                const float mn = fmaxf(m, s);
                const float cold = expf(m - mn);
                const float p = expf(s - mn);
                l = l * cold + p;
                a0 = a0 * cold + p * Vs[r][lane];
                a1 = a1 * cold + p * Vs[r][lane + 32];
                m = mn;
            }
        }

        if (active) {
            const float inv = 1.f / l;
            AOb[(size_t)myq * DIM + lane]      = tf32r(a0 * inv);
            AOb[(size_t)myq * DIM + lane + 32] = tf32r(a1 * inv);
        }
    }
}

// ---------------- launch ----------------
extern "C" void kernel_launch(void* const* d_in, const int* in_sizes, int n_in,
                              void* d_out, int out_size) {
    const float* query = (const float*)d_in[0];
    const float* key   = (const float*)d_in[1];
    const float* value = (const float*)d_in[2];
    const float* Wq = (const float*)d_in[3];
    const float* bq = (const float*)d_in[4];
    const float* Wk = (const float*)d_in[5];
    const float* bk = (const float*)d_in[6];
    const float* Wv = (const float*)d_in[7];
    const float* bv = (const float*)d_in[8];
    const float* Wo = (const float*)d_in[9];
    const float* bo = (const float*)d_in[10];
    const float* lsh = (const float*)d_in[11];
    float* out = (float*)d_out;

    cudaFuncSetAttribute(gemm_tf32_kernel,
                         cudaFuncAttributeMaxDynamicSharedMemorySize, TF32_SMEM_BYTES);

    const dim3 blk(256);

    // Round-12 launch order (466.9 best).
    roundX_kernel<<<dim3(MROWS * DIM / 1024, 3), blk>>>(query, key, value);    // 1
    transposeW_kernel<<<dim3(32, 32, 4), dim3(32, 8)>>>(Wq, Wk, Wv, Wo);       // 2
    nk64_part_kernel<<<dim3(DIM / 64, KSPLIT, 2), blk>>>(Wq, Wk, lsh, 0);      // 3

    // 4: tf32 input projections, batched z=3
    {
        GemmArgs ga;
        ga.bias[0] = bq; ga.bias[1] = bk; ga.bias[2] = bv;
        ga.Cext[0] = ga.Cext[1] = ga.Cext[2] = nullptr;
        ga.asel[0] = 4; ga.asel[1] = 5; ga.asel[2] = 6;
        ga.bwsel[0] = 0; ga.bwsel[1] = 1; ga.bwsel[2] = 2;
        ga.csel[0] = 0; ga.csel[1] = 1; ga.csel[2] = 2;
        gemm_tf32_kernel<<<dim3(DIM / TBN, MROWS / TBM, 3), blk, TF32_SMEM_BYTES>>>(ga, MROWS, DIM, DIM);
    }

    reduceT_kernel<<<dim3(DIM * NBUCKET / 512, 2), 512>>>();                   // 5
    bvec_kernel<<<dim3(NBUCKET, 2), 128>>>(bq, bk, lsh);                       // 6
    nk64_part_kernel<<<dim3(MROWS / 64, KSPLIT, 2), blk>>>(query, key, lsh, 1);// 7
    reduceP_argmax_kernel<<<dim3(MROWS / 8, 2), blk>>>();                      // 8
    sort_kernel<<<dim3(BATCH, 2), 1024>>>();                                   // 9

    meanv1_kernel<<<dim3(BATCH, 8), DIM>>>();                                  // 10
    meanv2_kernel<<<BATCH, DIM>>>();                                           // 11

    attn_bucket_kernel<<<dim3(NBUCKET, NHEAD, BATCH), blk>>>();                // 12

    // tf32 output projection (AO already tf32-rounded by attention)
    {
        GemmArgs ga;
        ga.bias[0] = bo; ga.bias[1] = nullptr; ga.bias[2] = nullptr;
        ga.Cext[0] = out; ga.Cext[1] = nullptr; ga.Cext[2] = nullptr;
        ga.asel[0] = 3; ga.asel[1] = 3; ga.asel[2] = 3;
        ga.bwsel[0] = 3; ga.bwsel[1] = 3; ga.bwsel[2] = 3;
        ga.csel[0] = -1; ga.csel[1] = -1; ga.csel[2] = -1;
        gemm_tf32_kernel<<<dim3(DIM / TBN, MROWS / TBM, 1), blk, TF32_SMEM_BYTES>>>(ga, MROWS, DIM, DIM);
    }
}